// round 1
// baseline (speedup 1.0000x reference)
#include <cuda_runtime.h>
#include <math.h>

#define BB 64
#define FF 240
#define JJ 22
#define NSEG 16
#define NPAIR 256
#define NPATH 5

// segment start/end joints (derived from KINEMATIC_CHAIN, paths = chain[1:])
__constant__ int c_seg_s[NSEG] = {2,5,8,  1,4,7,  3,6,9,12,  14,17,19,  13,16,18};
__constant__ int c_seg_e[NSEG] = {5,8,11, 4,7,10, 6,9,12,15, 17,19,21,  16,18,20};
// path -> contiguous segment range
__constant__ int c_path_off[NPATH] = {0,3,6,10,13};
__constant__ int c_path_cnt[NPATH] = {3,3,4,3,3};

// scratch: gli_pose [B,F,25] and bbox-overlap flag [B,F]
__device__ float g_pose[BB * FF * 25];
__device__ unsigned char g_flag[BB * FF];

struct V3 { float x, y, z; };

__device__ __forceinline__ V3 vsub(V3 a, V3 b) { return {a.x-b.x, a.y-b.y, a.z-b.z}; }
__device__ __forceinline__ V3 vcross(V3 a, V3 b) {
    return {a.y*b.z - a.z*b.y, a.z*b.x - a.x*b.z, a.x*b.y - a.y*b.x};
}
__device__ __forceinline__ float vdot(V3 a, V3 b) { return a.x*b.x + a.y*b.y + a.z*b.z; }
__device__ __forceinline__ V3 safe_norm(V3 v) {
    float ss = vdot(v, v);
    if (ss > 0.0f) {
        float inv = 1.0f / sqrtf(ss);
        return {v.x*inv, v.y*inv, v.z*inv};
    }
    return {0.0f, 0.0f, 0.0f};
}
__device__ __forceinline__ float asin_dot(V3 a, V3 b) {
    float d = vdot(a, b);
    d = fminf(fmaxf(d, -1.0f), 1.0f);
    return asinf(d);
}

// one CTA per frame; 256 threads = one per (seg_m, seg_n) pair
__global__ void __launch_bounds__(NPAIR) gli_frame_kernel(
    const float* __restrict__ motion1,
    const float* __restrict__ motion2)
{
    const int bf = blockIdx.x;          // b*FF + f
    const int tid = threadIdx.x;

    __shared__ float m1s[JJ * 3];
    __shared__ float m2s[JJ * 3];
    __shared__ float gbuf[NPAIR];

    const size_t base = (size_t)bf * (JJ * 3);
    if (tid < JJ * 3) {
        m1s[tid] = motion1[base + tid];
    } else if (tid < 2 * JJ * 3) {
        int k = tid - JJ * 3;
        m2s[k] = motion2[base + k];
    }
    __syncthreads();

    // ---- GLI for this segment pair ----
    {
        const int m = tid >> 4;
        const int n = tid & 15;
        const int js1 = 3 * c_seg_s[m], je1 = 3 * c_seg_e[m];
        const int js2 = 3 * c_seg_s[n], je2 = 3 * c_seg_e[n];
        V3 s1 = {m1s[js1], m1s[js1+1], m1s[js1+2]};
        V3 e1 = {m1s[je1], m1s[je1+1], m1s[je1+2]};
        V3 s2 = {m2s[js2], m2s[js2+1], m2s[js2+2]};
        V3 e2 = {m2s[je2], m2s[je2+1], m2s[je2+2]};

        V3 r13 = vsub(s2, s1);
        V3 r14 = vsub(e2, s1);
        V3 r23 = vsub(s2, e1);
        V3 r24 = vsub(e2, e1);
        V3 r12 = vsub(e1, s1);
        V3 r34 = vsub(e2, s2);

        V3 f0 = safe_norm(vcross(r13, r14));
        V3 f1 = safe_norm(vcross(r14, r24));
        V3 f2 = safe_norm(vcross(r24, r23));
        V3 f3 = safe_norm(vcross(r23, r13));

        float total = asin_dot(f0, f1) + asin_dot(f1, f2)
                    + asin_dot(f2, f3) + asin_dot(f3, f0);
        float sign = vdot(vcross(r34, r12), r13);
        float mult = (sign <= 0.0f) ? -1.0f : 1.0f;
        gbuf[tid] = mult * total * (1.0f / (4.0f * 3.14159265358979323846f));
    }
    __syncthreads();

    // ---- deterministic 5x5 path-block reduction (threads 0..24, warp 0) ----
    if (tid < 25) {
        const int i = tid / 5;
        const int j = tid % 5;
        const int mo = c_path_off[i], mc = c_path_cnt[i];
        const int no = c_path_off[j], nc = c_path_cnt[j];
        float s = 0.0f;
        for (int m = mo; m < mo + mc; ++m)
            for (int n = no; n < no + nc; ++n)
                s += gbuf[m * 16 + n];
        g_pose[(size_t)bf * 25 + tid] = s;
    }

    // ---- xz bbox overlap flag (thread 32, warp 1 — runs parallel to warp 0) ----
    if (tid == 32) {
        float nx1 =  1e30f, xx1 = -1e30f, nz1 =  1e30f, xz1 = -1e30f;
        float nx2 =  1e30f, xx2 = -1e30f, nz2 =  1e30f, xz2 = -1e30f;
        #pragma unroll
        for (int j = 0; j < JJ; ++j) {
            float x1 = m1s[3*j], z1 = m1s[3*j+2];
            float x2 = m2s[3*j], z2 = m2s[3*j+2];
            nx1 = fminf(nx1, x1); xx1 = fmaxf(xx1, x1);
            nz1 = fminf(nz1, z1); xz1 = fmaxf(xz1, z1);
            nx2 = fminf(nx2, x2); xx2 = fmaxf(xx2, x2);
            nz2 = fminf(nz2, z2); xz2 = fmaxf(xz2, z2);
        }
        bool fl = (xx1 >= nx2) && (xx2 >= nx1) && (xz1 >= nz2) && (xz2 >= nz1);
        g_flag[bf] = fl ? 1 : 0;
    }
}

// one thread per output element [B, F-1]
__global__ void vel_kernel(float* __restrict__ out)
{
    int idx = blockIdx.x * blockDim.x + threadIdx.x;
    const int total = BB * (FF - 1);
    if (idx >= total) return;
    const int b = idx / (FF - 1);
    const int f = idx % (FF - 1);
    const unsigned char* fl = &g_flag[b * FF];

    // dilated mask at frame t: flag[t-1] | flag[t] | flag[t+1] (zero-padded)
    auto maskAt = [&](int t) -> float {
        unsigned char v = fl[t];
        if (t > 0)      v |= fl[t - 1];
        if (t + 1 < FF) v |= fl[t + 1];
        return v ? 1.0f : 0.0f;
    };
    const float m0 = maskAt(f);
    const float m1 = maskAt(f + 1);

    const float* g0 = &g_pose[((size_t)b * FF + f) * 25];
    const float* g1 = g0 + 25;
    float vmax = 0.0f;
    #pragma unroll
    for (int k = 0; k < 25; ++k) {
        float d = fabsf(g1[k] * m1 - g0[k] * m0);
        vmax = fmaxf(vmax, d);
    }
    out[idx] = vmax;
}

extern "C" void kernel_launch(void* const* d_in, const int* in_sizes, int n_in,
                              void* d_out, int out_size)
{
    const float* motion1 = (const float*)d_in[0];
    const float* motion2 = (const float*)d_in[1];
    float* out = (float*)d_out;

    gli_frame_kernel<<<BB * FF, NPAIR>>>(motion1, motion2);

    const int total = BB * (FF - 1);
    vel_kernel<<<(total + 255) / 256, 256>>>(out);
}

// round 2
// speedup vs baseline: 1.3318x; 1.3318x over previous
#include <cuda_runtime.h>
#include <math.h>

#define BB 64
#define FF 240
#define JJ 22
#define NSEG 16
#define NPAIR 256
#define NPATH 5
#define BFTOT (BB * FF)

// segment start/end joints (derived from KINEMATIC_CHAIN, paths = chain[1:])
__constant__ int c_seg_s[NSEG] = {2,5,8,  1,4,7,  3,6,9,12,  14,17,19,  13,16,18};
__constant__ int c_seg_e[NSEG] = {5,8,11, 4,7,10, 6,9,12,15, 17,19,21,  16,18,20};
// path -> contiguous segment range
__constant__ int c_path_off[NPATH] = {0,3,6,10,13};
__constant__ int c_path_cnt[NPATH] = {3,3,4,3,3};

// scratch: gli_pose transposed [25][B*F] (coalesced reads in vel), flags [B*F]
__device__ float g_pose_t[25 * BFTOT];
__device__ unsigned char g_flag[BFTOT];

struct V3 { float x, y, z; };

__device__ __forceinline__ V3 vsub(V3 a, V3 b) { return {a.x-b.x, a.y-b.y, a.z-b.z}; }
__device__ __forceinline__ V3 vcross(V3 a, V3 b) {
    return {a.y*b.z - a.z*b.y, a.z*b.x - a.x*b.z, a.x*b.y - a.y*b.x};
}
__device__ __forceinline__ float vdot(V3 a, V3 b) { return a.x*b.x + a.y*b.y + a.z*b.z; }

// Newton-refined rsqrt: ~full fp32 accuracy, 1 MUFU + ~4 fma
__device__ __forceinline__ float rsqrt_ref(float x) {
    float y = rsqrtf(x);
    float e = x * y;
    return y * fmaf(-0.5f * e, y, 1.5f);
}

// normalized-dot of two raw (unnormalized) cross products with zero guard + clip
__device__ __forceinline__ float ndot(V3 ci, V3 cj, float ssi, float ssj) {
    float g = vdot(ci, cj);
    float p = ssi * ssj;
    float d = g * rsqrt_ref(p);
    d = (p > 0.0f) ? d : 0.0f;
    return fminf(fmaxf(d, -1.0f), 1.0f);
}

// branchless asin for x in [-1,1] (musl coefficients, ~1 ulp)
__device__ __forceinline__ float asin_clamped(float x) {
    float a = fabsf(x);
    bool big = a > 0.5f;
    float z = big ? fmaf(a, -0.5f, 0.5f) : a * a;       // (1-a)/2  or  a^2, z in [0,0.25]
    // sqrt(z) via refined rsqrt (guard z==0)
    float r = rsqrtf(z);
    float e = z * r;
    r = r * fmaf(-0.5f * e, r, 1.5f);
    float sq = z * r;
    sq = (z == 0.0f) ? 0.0f : sq;
    float s = big ? sq : a;
    // R(z) = z*(p0 + z*(p1 + z*p2)) / (1 + z*q1)
    float num = z * fmaf(z, fmaf(z, -8.6563630030e-03f, -4.2743422091e-02f), 1.6666586697e-01f);
    float den = fmaf(z, -7.0662963390e-01f, 1.0f);
    float R = __fdividef(num, den);
    float t = fmaf(s, R, s);                             // asin(s)
    float res = big ? fmaf(-2.0f, t, 1.5707963267948966f) : t;
    return copysignf(res, x);
}

// one CTA per frame; 256 threads = one per (seg_m, seg_n) pair
__global__ void __launch_bounds__(NPAIR) gli_frame_kernel(
    const float* __restrict__ motion1,
    const float* __restrict__ motion2)
{
    const int bf = blockIdx.x;          // b*FF + f
    const int tid = threadIdx.x;

    __shared__ float2 m1s2[33];
    __shared__ float2 m2s2[33];
    __shared__ float gbuf[NPAIR];
    float* m1s = (float*)m1s2;
    float* m2s = (float*)m2s2;

    // stage 66+66 floats as float2 (8B-aligned: 66 floats * 4B = 264B, 264%8==0)
    const size_t base2 = (size_t)bf * 33;   // in float2 units
    if (tid < 33) {
        m1s2[tid] = ((const float2*)motion1)[base2 + tid];
    } else if (tid < 66) {
        int k = tid - 33;
        m2s2[k] = ((const float2*)motion2)[base2 + k];
    }
    __syncthreads();

    // ---- GLI for this segment pair ----
    {
        const int m = tid >> 4;
        const int n = tid & 15;
        const int js1 = 3 * c_seg_s[m], je1 = 3 * c_seg_e[m];
        const int js2 = 3 * c_seg_s[n], je2 = 3 * c_seg_e[n];
        V3 s1 = {m1s[js1], m1s[js1+1], m1s[js1+2]};
        V3 e1 = {m1s[je1], m1s[je1+1], m1s[je1+2]};
        V3 s2 = {m2s[js2], m2s[js2+1], m2s[js2+2]};
        V3 e2 = {m2s[je2], m2s[je2+1], m2s[je2+2]};

        V3 r13 = vsub(s2, s1);
        V3 r14 = vsub(e2, s1);
        V3 r23 = vsub(s2, e1);
        V3 r24 = vsub(e2, e1);
        V3 r12 = vsub(e1, s1);
        V3 r34 = vsub(e2, s2);

        V3 c0 = vcross(r13, r14);
        V3 c1 = vcross(r14, r24);
        V3 c2 = vcross(r24, r23);
        V3 c3 = vcross(r23, r13);

        float ss0 = vdot(c0, c0);
        float ss1 = vdot(c1, c1);
        float ss2 = vdot(c2, c2);
        float ss3 = vdot(c3, c3);

        float d01 = ndot(c0, c1, ss0, ss1);
        float d12 = ndot(c1, c2, ss1, ss2);
        float d23 = ndot(c2, c3, ss2, ss3);
        float d30 = ndot(c3, c0, ss3, ss0);

        float total = asin_clamped(d01) + asin_clamped(d12)
                    + asin_clamped(d23) + asin_clamped(d30);
        float sign = vdot(vcross(r34, r12), r13);
        float mult = (sign <= 0.0f) ? -1.0f : 1.0f;
        gbuf[tid] = mult * total * (1.0f / (4.0f * 3.14159265358979323846f));
    }
    __syncthreads();

    // ---- deterministic 5x5 path-block reduction (threads 0..24, warp 0) ----
    if (tid < 25) {
        const int i = tid / 5;
        const int j = tid % 5;
        const int mo = c_path_off[i], mc = c_path_cnt[i];
        const int no = c_path_off[j], nc = c_path_cnt[j];
        float s = 0.0f;
        for (int m = mo; m < mo + mc; ++m)
            for (int n = no; n < no + nc; ++n)
                s += gbuf[m * 16 + n];
        g_pose_t[tid * BFTOT + bf] = s;   // transposed for coalesced vel reads
    }

    // ---- xz bbox overlap flag (thread 32, warp 1 — parallel to warp 0) ----
    if (tid == 32) {
        float nx1 =  1e30f, xx1 = -1e30f, nz1 =  1e30f, xz1 = -1e30f;
        float nx2 =  1e30f, xx2 = -1e30f, nz2 =  1e30f, xz2 = -1e30f;
        #pragma unroll
        for (int j = 0; j < JJ; ++j) {
            float x1 = m1s[3*j], z1 = m1s[3*j+2];
            float x2 = m2s[3*j], z2 = m2s[3*j+2];
            nx1 = fminf(nx1, x1); xx1 = fmaxf(xx1, x1);
            nz1 = fminf(nz1, z1); xz1 = fmaxf(xz1, z1);
            nx2 = fminf(nx2, x2); xx2 = fmaxf(xx2, x2);
            nz2 = fminf(nz2, z2); xz2 = fmaxf(xz2, z2);
        }
        bool fl = (xx1 >= nx2) && (xx2 >= nx1) && (xz1 >= nz2) && (xz2 >= nz1);
        g_flag[bf] = fl ? 1 : 0;
    }
}

// one thread per output element [B, F-1]; pose reads now coalesced (transposed)
__global__ void vel_kernel(float* __restrict__ out)
{
    int idx = blockIdx.x * blockDim.x + threadIdx.x;
    const int total = BB * (FF - 1);
    if (idx >= total) return;
    const int b = idx / (FF - 1);
    const int f = idx % (FF - 1);
    const int bf = b * FF + f;
    const unsigned char* fl = &g_flag[b * FF];

    // dilated mask at frame t: flag[t-1] | flag[t] | flag[t+1] (zero-padded)
    unsigned char fm1 = (f > 0) ? fl[f - 1] : 0;
    unsigned char f0  = fl[f];
    unsigned char f1  = fl[f + 1];
    unsigned char f2  = (f + 2 < FF) ? fl[f + 2] : 0;
    float m0 = (fm1 | f0 | f1) ? 1.0f : 0.0f;
    float m1 = (f0 | f1 | f2) ? 1.0f : 0.0f;

    float vmax = 0.0f;
    #pragma unroll
    for (int k = 0; k < 25; ++k) {
        const float* gp = &g_pose_t[k * BFTOT + bf];
        float d = fabsf(gp[1] * m1 - gp[0] * m0);
        vmax = fmaxf(vmax, d);
    }
    out[idx] = vmax;
}

extern "C" void kernel_launch(void* const* d_in, const int* in_sizes, int n_in,
                              void* d_out, int out_size)
{
    const float* motion1 = (const float*)d_in[0];
    const float* motion2 = (const float*)d_in[1];
    float* out = (float*)d_out;

    gli_frame_kernel<<<BB * FF, NPAIR>>>(motion1, motion2);

    const int total = BB * (FF - 1);
    vel_kernel<<<(total + 255) / 256, 256>>>(out);
}

// round 4
// speedup vs baseline: 1.7013x; 1.2774x over previous
#include <cuda_runtime.h>
#include <math.h>

#define BB 64
#define FF 240
#define JJ 22
#define NSEG 16
#define NPATH 5
#define BFTOT (BB * FF)
#define FPC 8            // frames per CTA = warps per CTA

// segment start/end joints (derived from KINEMATIC_CHAIN, paths = chain[1:])
__constant__ int c_seg_s[NSEG] = {2,5,8,  1,4,7,  3,6,9,12,  14,17,19,  13,16,18};
__constant__ int c_seg_e[NSEG] = {5,8,11, 4,7,10, 6,9,12,15, 17,19,21,  16,18,20};
__constant__ int c_path_off[NPATH] = {0,3,6,10,13};
__constant__ int c_path_cnt[NPATH] = {3,3,4,3,3};

// pose padded to 32 floats/frame for aligned, coalesced warp reads in vel
__device__ float g_pose[BFTOT * 32];
__device__ unsigned char g_flag[BFTOT];

struct V3 { float x, y, z; };

__device__ __forceinline__ V3 vsub(V3 a, V3 b) { return {a.x-b.x, a.y-b.y, a.z-b.z}; }
__device__ __forceinline__ V3 vcross(V3 a, V3 b) {
    return {a.y*b.z - a.z*b.y, a.z*b.x - a.x*b.z, a.x*b.y - a.y*b.x};
}
__device__ __forceinline__ float vdot(V3 a, V3 b) { return a.x*b.x + a.y*b.y + a.z*b.z; }
__device__ __forceinline__ V3 ld3(const float* p, int j) { return {p[j], p[j+1], p[j+2]}; }

// normalized-dot of raw cross products: raw MUFU rsqrt (~2 ulp, far within tolerance)
__device__ __forceinline__ float ndot(V3 ci, V3 cj, float ssi, float ssj) {
    float g = vdot(ci, cj);
    float p = ssi * ssj;
    float d = g * rsqrtf(p);
    d = (p > 0.0f) ? d : 0.0f;
    return fminf(fmaxf(d, -1.0f), 1.0f);
}

// branchless asin for x in [-1,1] (musl rational, MUFU sqrt/rcp)
__device__ __forceinline__ float asin_clamped(float x) {
    float a = fabsf(x);
    bool big = a > 0.5f;
    float z = big ? fmaf(a, -0.5f, 0.5f) : a * a;       // (1-a)/2 or a^2
    float sq = z * rsqrtf(z);                            // sqrt(z), z>0
    sq = (z == 0.0f) ? 0.0f : sq;
    float s = big ? sq : a;
    float num = z * fmaf(z, fmaf(z, -8.6563630030e-03f, -4.2743422091e-02f), 1.6666586697e-01f);
    float den = fmaf(z, -7.0662963390e-01f, 1.0f);
    float R = __fdividef(num, den);
    float t = fmaf(s, R, s);                             // asin(s)
    float res = big ? fmaf(-2.0f, t, 1.5707963267948966f) : t;
    return copysignf(res, x);
}

__device__ __forceinline__ float wmaxf(float v) {
    #pragma unroll
    for (int o = 16; o; o >>= 1) v = fmaxf(v, __shfl_xor_sync(0xffffffffu, v, o));
    return v;
}
__device__ __forceinline__ float wminf(float v) {
    #pragma unroll
    for (int o = 16; o; o >>= 1) v = fminf(v, __shfl_xor_sync(0xffffffffu, v, o));
    return v;
}

// one WARP per frame, 8 frames per CTA. No block barriers at all.
__global__ void __launch_bounds__(FPC * 32) gli_kernel(
    const float* __restrict__ motion1,
    const float* __restrict__ motion2)
{
    const int w    = threadIdx.x >> 5;
    const int lane = threadIdx.x & 31;
    const int bf   = blockIdx.x * FPC + w;

    __shared__ float2 jnt[FPC][2][33];   // [frame][tensor][float2], 66 floats each
    __shared__ float  gbuf[FPC][256];

    // stage this warp's frame joints (float2 vectorized); 33 elements need
    // 32 lanes + one extra load from lane 0 (FIX for Round-3 bug: element 32
    // = joint 21 y,z was never loaded by the 32-lane warp)
    {
        const float2* p1 = (const float2*)motion1 + (size_t)bf * 33;
        const float2* p2 = (const float2*)motion2 + (size_t)bf * 33;
        jnt[w][0][lane] = p1[lane];
        jnt[w][1][lane] = p2[lane];
        if (lane == 0) {
            jnt[w][0][32] = p1[32];
            jnt[w][1][32] = p2[32];
        }
    }
    __syncwarp();

    const float* m1s = (const float*)jnt[w][0];
    const float* m2s = (const float*)jnt[w][1];

    // ---- xz bbox overlap flag via warp shuffle reduction ----
    {
        bool ok = lane < JJ;
        float x1 = ok ? m1s[3*lane]     :  1e30f;
        float z1 = ok ? m1s[3*lane + 2] :  1e30f;
        float x2 = ok ? m2s[3*lane]     :  1e30f;
        float z2 = ok ? m2s[3*lane + 2] :  1e30f;
        float X1 = ok ? x1 : -1e30f, Z1 = ok ? z1 : -1e30f;
        float X2 = ok ? x2 : -1e30f, Z2 = ok ? z2 : -1e30f;
        float nx1 = wminf(x1), xx1 = wmaxf(X1);
        float nz1 = wminf(z1), xz1 = wmaxf(Z1);
        float nx2 = wminf(x2), xx2 = wmaxf(X2);
        float nz2 = wminf(z2), xz2 = wmaxf(Z2);
        if (lane == 0) {
            bool fl = (xx1 >= nx2) && (xx2 >= nx1) && (xz1 >= nz2) && (xz2 >= nz1);
            g_flag[bf] = fl ? 1 : 0;
        }
    }

    // ---- 8 GLIs per lane: pair p = i*32 + lane; m = 2i + (lane>>4); n = lane&15 ----
    const int n = lane & 15;
    const int h = lane >> 4;
    const V3 s2 = ld3(m2s, 3 * c_seg_s[n]);
    const V3 e2 = ld3(m2s, 3 * c_seg_e[n]);
    const V3 r34 = vsub(e2, s2);

    #pragma unroll 2
    for (int i = 0; i < 8; ++i) {
        const int m = 2 * i + h;
        const V3 s1 = ld3(m1s, 3 * c_seg_s[m]);
        const V3 e1 = ld3(m1s, 3 * c_seg_e[m]);

        V3 r13 = vsub(s2, s1);
        V3 r14 = vsub(e2, s1);
        V3 r23 = vsub(s2, e1);
        V3 r24 = vsub(e2, e1);
        V3 r12 = vsub(e1, s1);

        V3 c0 = vcross(r13, r14);
        V3 c1 = vcross(r14, r24);
        V3 c2 = vcross(r24, r23);
        V3 c3 = vcross(r23, r13);

        float ss0 = vdot(c0, c0);
        float ss1 = vdot(c1, c1);
        float ss2 = vdot(c2, c2);
        float ss3 = vdot(c3, c3);

        float total = asin_clamped(ndot(c0, c1, ss0, ss1))
                    + asin_clamped(ndot(c1, c2, ss1, ss2))
                    + asin_clamped(ndot(c2, c3, ss2, ss3))
                    + asin_clamped(ndot(c3, c0, ss3, ss0));

        float sign = vdot(vcross(r34, r12), r13);
        float mult = (sign <= 0.0f) ? -1.0f : 1.0f;
        gbuf[w][i * 32 + lane] = mult * total * (1.0f / (4.0f * 3.14159265358979323846f));
    }
    __syncwarp();

    // ---- 5x5 path-block sums (lanes 0..24), deterministic order ----
    if (lane < 25) {
        const int i = lane / 5;
        const int j = lane % 5;
        const int mo = c_path_off[i], mc = c_path_cnt[i];
        const int no = c_path_off[j], nc = c_path_cnt[j];
        float s = 0.0f;
        for (int m = mo; m < mo + mc; ++m)
            for (int nn = no; nn < no + nc; ++nn)
                s += gbuf[w][m * 16 + nn];
        g_pose[(size_t)bf * 32 + lane] = s;
    }
}

// one WARP per output element [B, F-1]: lanes 0..24 cover path pairs, shuffle-max
__global__ void __launch_bounds__(256) vel_kernel(float* __restrict__ out)
{
    const int gw   = (blockIdx.x * blockDim.x + threadIdx.x) >> 5;
    const int lane = threadIdx.x & 31;
    const int total = BB * (FF - 1);
    if (gw >= total) return;

    const int b = gw / (FF - 1);
    const int f = gw % (FF - 1);
    const int bf = b * FF + f;
    const unsigned char* fl = &g_flag[b * FF];

    unsigned char fm1 = (f > 0) ? fl[f - 1] : 0;
    unsigned char f0  = fl[f];
    unsigned char f1  = fl[f + 1];
    unsigned char f2  = (f + 2 < FF) ? fl[f + 2] : 0;
    float m0 = (fm1 | f0 | f1) ? 1.0f : 0.0f;
    float m1 = (f0 | f1 | f2) ? 1.0f : 0.0f;

    float d = 0.0f;
    if (lane < 25) {
        float p0 = g_pose[(size_t)bf * 32 + lane];
        float p1 = g_pose[(size_t)(bf + 1) * 32 + lane];
        d = fabsf(p1 * m1 - p0 * m0);
    }
    d = wmaxf(d);
    if (lane == 0) out[gw] = d;
}

extern "C" void kernel_launch(void* const* d_in, const int* in_sizes, int n_in,
                              void* d_out, int out_size)
{
    const float* motion1 = (const float*)d_in[0];
    const float* motion2 = (const float*)d_in[1];
    float* out = (float*)d_out;

    gli_kernel<<<BFTOT / FPC, FPC * 32>>>(motion1, motion2);

    const int nwarps = BB * (FF - 1);
    vel_kernel<<<(nwarps * 32 + 255) / 256, 256>>>(out);
}

// round 5
// speedup vs baseline: 1.8781x; 1.1040x over previous
#include <cuda_runtime.h>
#include <math.h>

#define BB 64
#define FF 240
#define JJ 22
#define NSEG 16
#define NPATH 5
#define BFTOT (BB * FF)
#define FPC 8            // frames per CTA = warps per CTA

__constant__ int c_seg_s[NSEG] = {2,5,8,  1,4,7,  3,6,9,12,  14,17,19,  13,16,18};
__constant__ int c_seg_e[NSEG] = {5,8,11, 4,7,10, 6,9,12,15, 17,19,21,  16,18,20};
__constant__ int c_path_off[NPATH] = {0,3,6,10,13};
__constant__ int c_path_cnt[NPATH] = {3,3,4,3,3};

__device__ float g_pose[BFTOT * 32];
__device__ unsigned char g_flag[BFTOT];

// ---------------- packed f32x2 primitives (sm_103a) ----------------
typedef unsigned long long f2;

__device__ __forceinline__ f2 pk2(float lo, float hi) {
    f2 r; asm("mov.b64 %0, {%1, %2};" : "=l"(r) : "f"(lo), "f"(hi)); return r;
}
__device__ __forceinline__ void upk2(float& lo, float& hi, f2 v) {
    asm("mov.b64 {%0, %1}, %2;" : "=f"(lo), "=f"(hi) : "l"(v));
}
__device__ __forceinline__ f2 bc(float v) {            // broadcast constant
    unsigned u = __float_as_uint(v);
    return ((f2)u << 32) | (f2)u;
}
__device__ __forceinline__ f2 f2fma(f2 a, f2 b, f2 c) {
    f2 r; asm("fma.rn.f32x2 %0, %1, %2, %3;" : "=l"(r) : "l"(a), "l"(b), "l"(c)); return r;
}
__device__ __forceinline__ f2 f2mul(f2 a, f2 b) {
    f2 r; asm("mul.rn.f32x2 %0, %1, %2;" : "=l"(r) : "l"(a), "l"(b)); return r;
}
__device__ __forceinline__ f2 f2add(f2 a, f2 b) {
    f2 r; asm("add.rn.f32x2 %0, %1, %2;" : "=l"(r) : "l"(a), "l"(b)); return r;
}
__device__ __forceinline__ f2 f2neg(f2 a) { return a ^ 0x8000000080000000ULL; }   // alu pipe
__device__ __forceinline__ f2 f2sub(f2 a, f2 b) { return f2add(a, f2neg(b)); }
__device__ __forceinline__ f2 f2abs(f2 a) { return a & 0x7FFFFFFF7FFFFFFFULL; }   // alu pipe

struct V3p { f2 x, y, z; };

__device__ __forceinline__ V3p p_sub(V3p a, V3p b) {
    return { f2sub(a.x,b.x), f2sub(a.y,b.y), f2sub(a.z,b.z) };
}
__device__ __forceinline__ V3p p_cross(V3p a, V3p b) {
    return { f2fma(a.y, b.z, f2neg(f2mul(a.z, b.y))),
             f2fma(a.z, b.x, f2neg(f2mul(a.x, b.z))),
             f2fma(a.x, b.y, f2neg(f2mul(a.y, b.x))) };
}
__device__ __forceinline__ f2 p_dot(V3p a, V3p b) {
    return f2fma(a.z, b.z, f2fma(a.y, b.y, f2mul(a.x, b.x)));
}

// normalized-dot of raw cross products, zero-guarded + clamped to [-1,1]
__device__ __forceinline__ f2 ndot2(const V3p& ci, const V3p& cj, f2 ssi, f2 ssj) {
    f2 g = p_dot(ci, cj);
    f2 p = f2mul(ssi, ssj);
    float pl, ph, gl, gh;
    upk2(pl, ph, p); upk2(gl, gh, g);
    float dl = gl * rsqrtf(pl);
    float dh = gh * rsqrtf(ph);
    dl = (pl > 0.0f) ? dl : 0.0f;
    dh = (ph > 0.0f) ? dh : 0.0f;
    dl = fminf(fmaxf(dl, -1.0f), 1.0f);      // FMNMX: alu pipe
    dh = fminf(fmaxf(dh, -1.0f), 1.0f);
    return pk2(dl, dh);
}

// packed asin for |x|<=1, cephes-style (~1e-7), one MUFU.RSQ per half
__device__ __forceinline__ f2 asin2(f2 x) {
    f2 ax = f2abs(x);
    f2 a2 = f2mul(ax, ax);
    f2 w  = f2fma(ax, bc(-0.5f), bc(0.5f));    // (1-a)/2
    float a2l, a2h, wl, wh, al, ah;
    upk2(a2l, a2h, a2); upk2(wl, wh, w); upk2(al, ah, ax);
    // exact identity: a<=0.5 -> a^2 <= (1-a)/2 ; a>=0.5 -> (1-a)/2 <= a^2
    float zl = fminf(a2l, wl), zh = fminf(a2h, wh);
    bool bigl = al > 0.5f, bigh = ah > 0.5f;
    float sql = zl * rsqrtf(zl); sql = (zl == 0.0f) ? 0.0f : sql;   // sqrt(z)
    float sqh = zh * rsqrtf(zh); sqh = (zh == 0.0f) ? 0.0f : sqh;
    float sl = bigl ? sql : al;
    float sh = bigh ? sqh : ah;
    f2 z = pk2(zl, zh);
    f2 s = pk2(sl, sh);
    f2 p = bc(4.2163199048e-2f);
    p = f2fma(p, z, bc(2.4181311049e-2f));
    p = f2fma(p, z, bc(4.5470025998e-2f));
    p = f2fma(p, z, bc(7.4953002686e-2f));
    p = f2fma(p, z, bc(1.6666752422e-1f));
    f2 t = f2fma(f2mul(s, z), p, s);            // asin(s) >= 0
    float tl, th;
    upk2(tl, th, t);
    float rl = bigl ? fmaf(-2.0f, tl, 1.5707963267948966f) : tl;
    float rh = bigh ? fmaf(-2.0f, th, 1.5707963267948966f) : th;
    // rl,rh >= 0: apply sign of x via OR of sign bits (alu pipe)
    return pk2(rl, rh) | (x & 0x8000000080000000ULL);
}

__device__ __forceinline__ float wmaxf(float v) {
    #pragma unroll
    for (int o = 16; o; o >>= 1) v = fmaxf(v, __shfl_xor_sync(0xffffffffu, v, o));
    return v;
}
__device__ __forceinline__ float wminf(float v) {
    #pragma unroll
    for (int o = 16; o; o >>= 1) v = fminf(v, __shfl_xor_sync(0xffffffffu, v, o));
    return v;
}

// one WARP per frame, 8 frames per CTA; each lane packs 2 GLI pairs per step
__global__ void __launch_bounds__(FPC * 32) gli_kernel(
    const float* __restrict__ motion1,
    const float* __restrict__ motion2)
{
    const int w    = threadIdx.x >> 5;
    const int lane = threadIdx.x & 31;
    const int bf   = blockIdx.x * FPC + w;

    __shared__ float2 jnt[FPC][2][33];
    __shared__ float  gbuf[FPC][256];

    {
        const float2* p1 = (const float2*)motion1 + (size_t)bf * 33;
        const float2* p2 = (const float2*)motion2 + (size_t)bf * 33;
        jnt[w][0][lane] = p1[lane];
        jnt[w][1][lane] = p2[lane];
        if (lane == 0) {           // element 32 (joint 21 y,z)
            jnt[w][0][32] = p1[32];
            jnt[w][1][32] = p2[32];
        }
    }
    __syncwarp();

    const float* m1s = (const float*)jnt[w][0];
    const float* m2s = (const float*)jnt[w][1];

    // ---- xz bbox overlap flag via warp shuffle reduction ----
    {
        bool ok = lane < JJ;
        float x1 = ok ? m1s[3*lane]     :  1e30f;
        float z1 = ok ? m1s[3*lane + 2] :  1e30f;
        float x2 = ok ? m2s[3*lane]     :  1e30f;
        float z2 = ok ? m2s[3*lane + 2] :  1e30f;
        float X1 = ok ? x1 : -1e30f, Z1 = ok ? z1 : -1e30f;
        float X2 = ok ? x2 : -1e30f, Z2 = ok ? z2 : -1e30f;
        float nx1 = wminf(x1), xx1 = wmaxf(X1);
        float nz1 = wminf(z1), xz1 = wmaxf(Z1);
        float nx2 = wminf(x2), xx2 = wmaxf(X2);
        float nz2 = wminf(z2), xz2 = wmaxf(Z2);
        if (lane == 0) {
            bool fl = (xx1 >= nx2) && (xx2 >= nx1) && (xz1 >= nz2) && (xz2 >= nz1);
            g_flag[bf] = fl ? 1 : 0;
        }
    }

    // ---- packed GLI: lane covers n = lane&15; m pairs (2i+h, 2i+h+8), i=0..3 ----
    const int n = lane & 15;
    const int h = lane >> 4;
    const int js2 = 3 * c_seg_s[n], je2 = 3 * c_seg_e[n];
    const V3p s2p = { bc(m2s[js2]), bc(m2s[js2+1]), bc(m2s[js2+2]) };
    const V3p e2p = { bc(m2s[je2]), bc(m2s[je2+1]), bc(m2s[je2+2]) };
    const float INV4PI = 0.07957747154594767f;

    #pragma unroll
    for (int i = 0; i < 4; ++i) {
        const int mlo = 2 * i + h;
        const int mhi = mlo + 8;
        const int sa = 3 * c_seg_s[mlo], sb = 3 * c_seg_s[mhi];
        const int ea = 3 * c_seg_e[mlo], eb = 3 * c_seg_e[mhi];
        V3p s1p = { pk2(m1s[sa], m1s[sb]), pk2(m1s[sa+1], m1s[sb+1]), pk2(m1s[sa+2], m1s[sb+2]) };
        V3p e1p = { pk2(m1s[ea], m1s[eb]), pk2(m1s[ea+1], m1s[eb+1]), pk2(m1s[ea+2], m1s[eb+2]) };

        V3p r13 = p_sub(s2p, s1p);
        V3p r14 = p_sub(e2p, s1p);
        V3p r12 = p_sub(e1p, s1p);

        // c0 = A, c1 = B, c3 = -C, c2 = B - A - C,  r34 x r12 = C - B
        V3p A  = p_cross(r13, r14);
        V3p Bv = p_cross(r12, r14);
        V3p Cv = p_cross(r12, r13);
        V3p c2v = { f2sub(f2sub(Bv.x, A.x), Cv.x),
                    f2sub(f2sub(Bv.y, A.y), Cv.y),
                    f2sub(f2sub(Bv.z, A.z), Cv.z) };

        f2 ss0 = p_dot(A, A);
        f2 ss1 = p_dot(Bv, Bv);
        f2 ss2 = p_dot(c2v, c2v);
        f2 ss3 = p_dot(Cv, Cv);

        f2 t01 = asin2(ndot2(A,  Bv,  ss0, ss1));
        f2 t12 = asin2(ndot2(Bv, c2v, ss1, ss2));
        f2 t23 = asin2(ndot2(c2v, Cv, ss2, ss3));   // = -asin(d23)
        f2 t30 = asin2(ndot2(Cv, A,  ss3, ss0));    // = -asin(d30)
        f2 tot = f2sub(f2add(t01, t12), f2add(t23, t30));

        V3p cb = p_sub(Cv, Bv);                     // r34 x r12
        f2 sg = p_dot(cb, r13);

        float sgl, sgh, totl, toth;
        upk2(sgl, sgh, sg); upk2(totl, toth, tot);
        float outl = totl * ((sgl <= 0.0f) ? -INV4PI : INV4PI);
        float outh = toth * ((sgh <= 0.0f) ? -INV4PI : INV4PI);
        gbuf[w][mlo * 16 + n] = outl;
        gbuf[w][mhi * 16 + n] = outh;
    }
    __syncwarp();

    // ---- 5x5 path-block sums (lanes 0..24), deterministic order ----
    if (lane < 25) {
        const int i = lane / 5;
        const int j = lane % 5;
        const int mo = c_path_off[i], mc = c_path_cnt[i];
        const int no = c_path_off[j], nc = c_path_cnt[j];
        float s = 0.0f;
        for (int m = mo; m < mo + mc; ++m)
            for (int nn = no; nn < no + nc; ++nn)
                s += gbuf[w][m * 16 + nn];
        g_pose[(size_t)bf * 32 + lane] = s;
    }
}

// one WARP per output element [B, F-1]
__global__ void __launch_bounds__(256) vel_kernel(float* __restrict__ out)
{
    const int gw   = (blockIdx.x * blockDim.x + threadIdx.x) >> 5;
    const int lane = threadIdx.x & 31;
    const int total = BB * (FF - 1);
    if (gw >= total) return;

    const int b = gw / (FF - 1);
    const int f = gw % (FF - 1);
    const int bf = b * FF + f;
    const unsigned char* fl = &g_flag[b * FF];

    unsigned char fm1 = (f > 0) ? fl[f - 1] : 0;
    unsigned char f0  = fl[f];
    unsigned char f1  = fl[f + 1];
    unsigned char f2_ = (f + 2 < FF) ? fl[f + 2] : 0;
    float m0 = (fm1 | f0 | f1) ? 1.0f : 0.0f;
    float m1 = (f0 | f1 | f2_) ? 1.0f : 0.0f;

    float d = 0.0f;
    if (lane < 25) {
        float p0 = g_pose[(size_t)bf * 32 + lane];
        float p1 = g_pose[(size_t)(bf + 1) * 32 + lane];
        d = fabsf(p1 * m1 - p0 * m0);
    }
    d = wmaxf(d);
    if (lane == 0) out[gw] = d;
}

extern "C" void kernel_launch(void* const* d_in, const int* in_sizes, int n_in,
                              void* d_out, int out_size)
{
    const float* motion1 = (const float*)d_in[0];
    const float* motion2 = (const float*)d_in[1];
    float* out = (float*)d_out;

    gli_kernel<<<BFTOT / FPC, FPC * 32>>>(motion1, motion2);

    const int nwarps = BB * (FF - 1);
    vel_kernel<<<(nwarps * 32 + 255) / 256, 256>>>(out);
}